// round 1
// baseline (speedup 1.0000x reference)
#include <cuda_runtime.h>

#define NUM_STEPS 20
#define DT_HALF (0.5f * (1.0f / 20.0f))   // DT/2 = (GATE_TIME/NUM_STEPS)/2

// cos(theta_total), sin(theta_total)
__device__ float g_cs[2];

__global__ void reduce_amps_kernel(const float* __restrict__ amps) {
    // single thread: 20 adds, one sincos
    float th = 0.f;
    #pragma unroll
    for (int k = 0; k < NUM_STEPS; ++k) th += amps[k];
    th *= DT_HALF;
    float s, c;
    __sincosf(th, &s, &c);
    // use accurate versions to be safe on precision
    g_cs[0] = cosf(th);
    g_cs[1] = sinf(th);
    (void)s; (void)c;
}

__global__ void __launch_bounds__(256) rotate_kernel(
    const float4* __restrict__ r0, const float4* __restrict__ r1,
    const float4* __restrict__ i0, const float4* __restrict__ i1,
    float4* __restrict__ or0, float4* __restrict__ or1,
    float4* __restrict__ oi0, float4* __restrict__ oi1,
    int n4)
{
    int idx = blockIdx.x * blockDim.x + threadIdx.x;
    if (idx >= n4) return;

    const float c = g_cs[0];
    const float s = g_cs[1];

    float4 a0 = r0[idx];
    float4 a1 = r1[idx];
    float4 b0 = i0[idx];
    float4 b1 = i1[idx];

    float4 vr0, vr1, vi0, vi1;
    vr0.x = fmaf(c, a0.x,  s * b1.x);
    vr0.y = fmaf(c, a0.y,  s * b1.y);
    vr0.z = fmaf(c, a0.z,  s * b1.z);
    vr0.w = fmaf(c, a0.w,  s * b1.w);

    vr1.x = fmaf(c, a1.x,  s * b0.x);
    vr1.y = fmaf(c, a1.y,  s * b0.y);
    vr1.z = fmaf(c, a1.z,  s * b0.z);
    vr1.w = fmaf(c, a1.w,  s * b0.w);

    vi0.x = fmaf(c, b0.x, -s * a1.x);
    vi0.y = fmaf(c, b0.y, -s * a1.y);
    vi0.z = fmaf(c, b0.z, -s * a1.z);
    vi0.w = fmaf(c, b0.w, -s * a1.w);

    vi1.x = fmaf(c, b1.x, -s * a0.x);
    vi1.y = fmaf(c, b1.y, -s * a0.y);
    vi1.z = fmaf(c, b1.z, -s * a0.z);
    vi1.w = fmaf(c, b1.w, -s * a0.w);

    or0[idx] = vr0;
    or1[idx] = vr1;
    oi0[idx] = vi0;
    oi1[idx] = vi1;
}

extern "C" void kernel_launch(void* const* d_in, const int* in_sizes, int n_in,
                              void* d_out, int out_size) {
    const float* amps       = (const float*)d_in[0];   // [20]
    const float* state_real = (const float*)d_in[1];   // [2, B]
    const float* state_imag = (const float*)d_in[2];   // [2, B]
    float* out = (float*)d_out;                        // [2, 2, B]

    const int B  = in_sizes[1] / 2;   // 8388608
    const int n4 = B / 4;             // B divisible by 4

    reduce_amps_kernel<<<1, 1>>>(amps);

    const float4* r0 = (const float4*)(state_real);
    const float4* r1 = (const float4*)(state_real + B);
    const float4* i0 = (const float4*)(state_imag);
    const float4* i1 = (const float4*)(state_imag + B);

    float4* or0 = (float4*)(out);
    float4* or1 = (float4*)(out + (size_t)B);
    float4* oi0 = (float4*)(out + 2 * (size_t)B);
    float4* oi1 = (float4*)(out + 3 * (size_t)B);

    int threads = 256;
    int blocks  = (n4 + threads - 1) / threads;
    rotate_kernel<<<blocks, threads>>>(r0, r1, i0, i1, or0, or1, oi0, oi1, n4);
}

// round 2
// speedup vs baseline: 1.0150x; 1.0150x over previous
#include <cuda_runtime.h>

#define NUM_STEPS 20
#define DT_HALF (0.5f * (1.0f / 20.0f))   // DT/2 = (GATE_TIME/NUM_STEPS)/2

// Each thread processes 2 float4 per stream: element (blockIdx*512 + tid) and (+256).
__global__ void __launch_bounds__(256) grape_fused_kernel(
    const float* __restrict__ amps,
    const float4* __restrict__ r0, const float4* __restrict__ r1,
    const float4* __restrict__ i0, const float4* __restrict__ i1,
    float4* __restrict__ or0, float4* __restrict__ or1,
    float4* __restrict__ oi0, float4* __restrict__ oi1,
    int n4)
{
    // Uniform angle: every thread sums the 20 amplitudes (broadcast loads).
    float th = 0.f;
    #pragma unroll
    for (int k = 0; k < NUM_STEPS; ++k) th += __ldg(&amps[k]);
    th *= DT_HALF;
    float s, c;
    sincosf(th, &s, &c);

    const int e0 = blockIdx.x * 512 + threadIdx.x;
    const int e1 = e0 + 256;

    // Front-batch all loads for max MLP.
    float4 a0_0, a1_0, b0_0, b1_0;
    float4 a0_1, a1_1, b0_1, b1_1;
    bool p0 = (e0 < n4);
    bool p1 = (e1 < n4);
    if (p0) { a0_0 = r0[e0]; a1_0 = r1[e0]; b0_0 = i0[e0]; b1_0 = i1[e0]; }
    if (p1) { a0_1 = r0[e1]; a1_1 = r1[e1]; b0_1 = i0[e1]; b1_1 = i1[e1]; }

#define ROT(a0, a1, b0, b1, vr0, vr1, vi0, vi1)            \
    do {                                                   \
        vr0.x = fmaf(c, a0.x,  s * b1.x);                  \
        vr0.y = fmaf(c, a0.y,  s * b1.y);                  \
        vr0.z = fmaf(c, a0.z,  s * b1.z);                  \
        vr0.w = fmaf(c, a0.w,  s * b1.w);                  \
        vr1.x = fmaf(c, a1.x,  s * b0.x);                  \
        vr1.y = fmaf(c, a1.y,  s * b0.y);                  \
        vr1.z = fmaf(c, a1.z,  s * b0.z);                  \
        vr1.w = fmaf(c, a1.w,  s * b0.w);                  \
        vi0.x = fmaf(c, b0.x, -s * a1.x);                  \
        vi0.y = fmaf(c, b0.y, -s * a1.y);                  \
        vi0.z = fmaf(c, b0.z, -s * a1.z);                  \
        vi0.w = fmaf(c, b0.w, -s * a1.w);                  \
        vi1.x = fmaf(c, b1.x, -s * a0.x);                  \
        vi1.y = fmaf(c, b1.y, -s * a0.y);                  \
        vi1.z = fmaf(c, b1.z, -s * a0.z);                  \
        vi1.w = fmaf(c, b1.w, -s * a0.w);                  \
    } while (0)

    if (p0) {
        float4 vr0, vr1, vi0, vi1;
        ROT(a0_0, a1_0, b0_0, b1_0, vr0, vr1, vi0, vi1);
        or0[e0] = vr0; or1[e0] = vr1; oi0[e0] = vi0; oi1[e0] = vi1;
    }
    if (p1) {
        float4 vr0, vr1, vi0, vi1;
        ROT(a0_1, a1_1, b0_1, b1_1, vr0, vr1, vi0, vi1);
        or0[e1] = vr0; or1[e1] = vr1; oi0[e1] = vi0; oi1[e1] = vi1;
    }
#undef ROT
}

extern "C" void kernel_launch(void* const* d_in, const int* in_sizes, int n_in,
                              void* d_out, int out_size) {
    const float* amps       = (const float*)d_in[0];   // [20]
    const float* state_real = (const float*)d_in[1];   // [2, B]
    const float* state_imag = (const float*)d_in[2];   // [2, B]
    float* out = (float*)d_out;                        // [2, 2, B]

    const int B  = in_sizes[1] / 2;   // 8388608
    const int n4 = B / 4;             // 2097152 float4 per stream

    const float4* r0 = (const float4*)(state_real);
    const float4* r1 = (const float4*)(state_real + B);
    const float4* i0 = (const float4*)(state_imag);
    const float4* i1 = (const float4*)(state_imag + B);

    float4* or0 = (float4*)(out);
    float4* or1 = (float4*)(out + (size_t)B);
    float4* oi0 = (float4*)(out + 2 * (size_t)B);
    float4* oi1 = (float4*)(out + 3 * (size_t)B);

    // 512 float4 per stream per block
    int blocks = (n4 + 511) / 512;
    grape_fused_kernel<<<blocks, 256>>>(amps, r0, r1, i0, i1,
                                        or0, or1, oi0, oi1, n4);
}